// round 11
// baseline (speedup 1.0000x reference)
#include <cuda_runtime.h>
#include <cstdint>
#include <math.h>

// Problem constants (fixed by setup_inputs)
#define BB   256   // batch
#define CTXD 512
#define DOF  6
#define WSZ  300
#define ZD   306   // DOF + WSZ
#define PGD  256
#define PWD  512
#define HGD  256
#define HWD  512
#define NL   2
#define MS   20
#define NSTEP (MS - 1)

// ---------------- scratch (device globals; no runtime allocation) ------------
__device__ __align__(16) float g_Aw[(size_t)PWD * BB * ZD];  // [o][b][j] fp32 (~160MB)
__device__ __align__(16) float g_Ag[BB * PGD * DOF];         // [b][o][j]
__device__ __align__(16) float g_x0[BB * PGD];
__device__ __align__(16) float g_y0[BB * PWD];
__device__ __align__(16) float g_x [BB * PGD];
__device__ __align__(16) float g_y [BB * PWD];
__device__ __align__(16) float g_Gg[BB * 4 * HGD];
__device__ __align__(16) float g_Gw[BB * 4 * HWD];
__device__ __align__(16) float g_hg[NL * 2 * BB * HGD];      // [layer][parity][b*H]
__device__ __align__(16) float g_cg[NL * BB * HGD];
__device__ __align__(16) float g_hw[NL * 2 * BB * HWD];
__device__ __align__(16) float g_cw[NL * BB * HWD];
__device__ __align__(16) float g_pg[BB * DOF];
__device__ __align__(16) float g_pw[BB * WSZ];

__device__ __forceinline__ float sigf(float x) { return 1.f / (1.f + expf(-x)); }

__device__ __forceinline__ float f2tf_f(float x) {
    uint32_t r;
    asm("cvt.rna.tf32.f32 %0, %1;" : "=r"(r) : "f"(x));
    return __uint_as_float(r);
}
// 3xTF32 split: x = hi + lo with hi=tf32(x), lo=tf32(x-hi); error ~2^-23
__device__ __forceinline__ void split_tf(float x, float& hi, float& lo) {
    hi = f2tf_f(x);
    lo = f2tf_f(x - hi);
}

__device__ __forceinline__ void mma8(float* d, const uint32_t* a, const uint32_t* b) {
    asm("mma.sync.aligned.m16n8k8.row.col.f32.tf32.tf32.f32 "
        "{%0,%1,%2,%3}, {%4,%5,%6,%7}, {%8,%9}, {%0,%1,%2,%3};"
        : "+f"(d[0]), "+f"(d[1]), "+f"(d[2]), "+f"(d[3])
        : "r"(a[0]), "r"(a[1]), "r"(a[2]), "r"(a[3]), "r"(b[0]), "r"(b[1]));
}

// ---------------- init: zero states, seed pg/pw, write t=0 outputs -----------
__global__ void init_kernel(const float* __restrict__ goal0,
                            const float* __restrict__ w0,
                            float* __restrict__ out)
{
    int tid0 = blockIdx.x * blockDim.x + threadIdx.x;
    int stride = gridDim.x * blockDim.x;
    for (int i = tid0; i < NL * BB * HGD; i += stride) {
        int l = i / (BB * HGD); int r = i % (BB * HGD);
        g_hg[(l * 2 + 0) * BB * HGD + r] = 0.f;
        g_cg[i] = 0.f;
    }
    for (int i = tid0; i < NL * BB * HWD; i += stride) {
        int l = i / (BB * HWD); int r = i % (BB * HWD);
        g_hw[(l * 2 + 0) * BB * HWD + r] = 0.f;
        g_cw[i] = 0.f;
    }
    for (int i = tid0; i < BB * DOF; i += stride) {
        float v = goal0[i];
        g_pg[i] = v;
        int b = i / DOF, d = i % DOF;
        out[b * (MS * DOF) + d] = v;                      // goals[:,0,:]
    }
    for (int i = tid0; i < BB * WSZ; i += stride) {
        float v = w0[i];
        g_pw[i] = v;
        int b = i / WSZ, c = i % WSZ;
        out[BB * MS * DOF + b * (MS * WSZ) + c] = v;      // ws[:,0,:]
    }
}

// ---------------- Ag[b][o][j] = sum_i ctx[b,i] * bgW[o,i,j] (fp32, tiny) -----
__global__ void pre_ag_kernel(const float* __restrict__ ctx,
                              const float* __restrict__ bgW)
{
    __shared__ float Ws[CTXD][DOF];  // 12KB
    int o = blockIdx.x;
    const float* Wo = bgW + (size_t)o * CTXD * DOF;
    for (int idx = threadIdx.x; idx < CTXD * DOF; idx += blockDim.x)
        Ws[idx / DOF][idx % DOF] = Wo[idx];
    __syncthreads();
    int b = threadIdx.x;  // blockDim.x == 256
    float acc[DOF] = {0.f, 0.f, 0.f, 0.f, 0.f, 0.f};
    const float* cr = ctx + (size_t)b * CTXD;
    for (int i = 0; i < CTXD; i++) {
        float c = cr[i];
#pragma unroll
        for (int j = 0; j < DOF; j++) acc[j] += c * Ws[i][j];
    }
    float* dst = g_Ag + ((size_t)b * PGD + o) * DOF;
#pragma unroll
    for (int j = 0; j < DOF; j++) dst[j] = acc[j];
}

// ---------------- pre_aw (3xTF32 tensor cores, fp32-accurate) ----------------
// Per o: D[b, j] = ctx[b, :] @ Wo[:, j].  A-op = ctx (row-major, k contig),
// B-op = Wo smem [k][j] (pad 72). Ktile=16. Output -> g_Aw[o][b][j] fp32.
__global__ void pre_aw_tc(const float* __restrict__ ctx,
                          const float* __restrict__ bwW)
{
    int o    = blockIdx.z;
    int bblk = blockIdx.x * 128;  // batch tile
    int jblk = blockIdx.y * 64;   // j tile
    const float* Wo = bwW + (size_t)o * CTXD * ZD;

    __shared__ float Ah[128 * 20], Al[128 * 20];  // ctx hi/lo [b][k16] pad20
    __shared__ float Bh[16 * 72],  Bl[16 * 72];   // Wo  hi/lo [k][j64] pad72

    int tid = threadIdx.x;
    int w = tid >> 5, lane = tid & 31;
    int g = lane >> 2, t = lane & 3;
    int wb = (w & 3) * 32;   // warp b offset (m16 dim)
    int wj = (w >> 2) * 32;  // warp j offset (n8 dim)

    float d[2][4][4] = {};

    for (int k0 = 0; k0 < CTXD; k0 += 16) {
        // stage ctx -> Ah/Al (128x16 = 512 float4)
        for (int idx = tid; idx < 512; idx += 256) {
            int m = idx >> 2, kq = (idx & 3) << 2;
            float4 v = *(const float4*)(ctx + (size_t)(bblk + m) * CTXD + k0 + kq);
            float h0, l0, h1, l1, h2, l2, h3, l3;
            split_tf(v.x, h0, l0); split_tf(v.y, h1, l1);
            split_tf(v.z, h2, l2); split_tf(v.w, h3, l3);
            int b0 = m * 20 + kq;
            Ah[b0] = h0; Ah[b0 + 1] = h1; Ah[b0 + 2] = h2; Ah[b0 + 3] = h3;
            Al[b0] = l0; Al[b0 + 1] = l1; Al[b0 + 2] = l2; Al[b0 + 3] = l3;
        }
        // stage Wo rows -> Bh/Bl (16x64 scalars; j tail guarded)
        for (int idx = tid; idx < 1024; idx += 256) {
            int k = idx >> 6, j = idx & 63;
            int gj = jblk + j;
            float v = (gj < ZD) ? Wo[(size_t)(k0 + k) * ZD + gj] : 0.f;
            float h, l; split_tf(v, h, l);
            Bh[k * 72 + j] = h; Bl[k * 72 + j] = l;
        }
        __syncthreads();
#pragma unroll
        for (int kk = 0; kk < 16; kk += 8) {
            uint32_t ah[2][4], al[2][4], bh[4][2], bl[4][2];
#pragma unroll
            for (int in = 0; in < 2; in++) {
                int base = (wb + in * 16 + g) * 20 + kk + t;
                ah[in][0] = __float_as_uint(Ah[base]);
                ah[in][1] = __float_as_uint(Ah[base + 8 * 20]);
                ah[in][2] = __float_as_uint(Ah[base + 4]);
                ah[in][3] = __float_as_uint(Ah[base + 8 * 20 + 4]);
                al[in][0] = __float_as_uint(Al[base]);
                al[in][1] = __float_as_uint(Al[base + 8 * 20]);
                al[in][2] = __float_as_uint(Al[base + 4]);
                al[in][3] = __float_as_uint(Al[base + 8 * 20 + 4]);
            }
#pragma unroll
            for (int jm = 0; jm < 4; jm++) {
                int col = wj + jm * 8 + g;
                bh[jm][0] = __float_as_uint(Bh[(kk + t) * 72 + col]);
                bh[jm][1] = __float_as_uint(Bh[(kk + t + 4) * 72 + col]);
                bl[jm][0] = __float_as_uint(Bl[(kk + t) * 72 + col]);
                bl[jm][1] = __float_as_uint(Bl[(kk + t + 4) * 72 + col]);
            }
#pragma unroll
            for (int in = 0; in < 2; in++)
#pragma unroll
                for (int jm = 0; jm < 4; jm++) {
                    mma8(d[in][jm], ah[in], bl[jm]);
                    mma8(d[in][jm], al[in], bh[jm]);
                    mma8(d[in][jm], ah[in], bh[jm]);
                }
        }
        __syncthreads();
    }
    // epilogue: write fp32 Aw[o][b][j]
    float* base = g_Aw + (size_t)o * BB * ZD;
#pragma unroll
    for (int in = 0; in < 2; in++) {
#pragma unroll
        for (int jm = 0; jm < 4; jm++) {
            int b0 = bblk + wb + in * 16 + g;
            int j0 = jblk + wj + jm * 8 + 2 * t;
            float* r = d[in][jm];
            if (j0 < ZD)     base[(size_t)b0 * ZD + j0]           = r[0];
            if (j0 + 1 < ZD) base[(size_t)b0 * ZD + j0 + 1]       = r[1];
            if (j0 < ZD)     base[(size_t)(b0 + 8) * ZD + j0]     = r[2];
            if (j0 + 1 < ZD) base[(size_t)(b0 + 8) * ZD + j0 + 1] = r[3];
        }
    }
}

// ---------------- per-step bilinears: x0 (Ag·pg), y0 (Aw·z), fp32 ------------
__global__ void bilinear_kernel(const float* __restrict__ bg_b,
                                const float* __restrict__ bw_b)
{
    if (blockIdx.x < 2048) {
        int b  = blockIdx.x >> 3;
        int og = (blockIdx.x & 7) * 64;
        __shared__ float zs[320];
        int tid = threadIdx.x;
        for (int i = tid; i < 320; i += 256) {
            float v = 0.f;
            if (i < DOF)      v = g_pg[b * DOF + i];
            else if (i < ZD)  v = g_pw[b * WSZ + (i - DOF)];
            zs[i] = v;
        }
        __syncthreads();
        int warp = tid >> 5, lane = tid & 31;
#pragma unroll
        for (int q = 0; q < 8; q++) {
            int o = og + warp * 8 + q;
            const float* row = g_Aw + ((size_t)o * BB + b) * ZD;
            float acc = 0.f;
            for (int j = lane; j < ZD; j += 32) acc += row[j] * zs[j];
#pragma unroll
            for (int off = 16; off > 0; off >>= 1)
                acc += __shfl_down_sync(0xffffffffu, acc, off);
            if (lane == 0) g_y0[b * PWD + o] = acc + bw_b[o];
        }
    } else {
        int b = blockIdx.x - 2048;
        __shared__ float ps[8];
        if (threadIdx.x < DOF) ps[threadIdx.x] = g_pg[b * DOF + threadIdx.x];
        __syncthreads();
        int o = threadIdx.x;  // 256 threads
        const float* ar = g_Ag + ((size_t)b * PGD + o) * DOF;
        float acc = bg_b[o];
#pragma unroll
        for (int j = 0; j < DOF; j++) acc += ar[j] * ps[j];
        g_x0[b * PGD + o] = acc;
    }
}

// ---------------- 3xTF32 dual GEMM: C = act(A1@W1^T + A2@W2^T + b) -----------
// Computed as C^T = W@A^T: A-op = W [N][K] row-major, B-op = act [M][K].
// Block tile: 128 N-rows x 64 M-cols, Ktile=16, fp32-accurate via hi/lo split.
struct TCJob {
    const float* A1; const float* W1;
    const float* A2; const float* W2;
    const float* b1; const float* b2;
    float* C;  float* C2;
    int K1, K2, N, ldc, ldc2, act, nbn;  // nbm fixed = 4 (256/64)
};

__global__ void tc_gemm2(TCJob j0, TCJob j1, int nblk0)
{
    TCJob jb  = (blockIdx.x < (unsigned)nblk0) ? j0 : j1;
    int local = blockIdx.x - ((blockIdx.x < (unsigned)nblk0) ? 0 : nblk0);
    int mblk  = (local & 3) * 64;    // batch offset
    int nblk  = (local >> 2) * 128;  // feature offset

    __shared__ float Ah[128 * 20], Al[128 * 20];  // W hi/lo   [n][k16] pad20
    __shared__ float Bh[64 * 20],  Bl[64 * 20];   // act hi/lo [m][k16] pad20

    int tid = threadIdx.x;
    int w = tid >> 5, lane = tid & 31;
    int g = lane >> 2, t = lane & 3;
    int wn = (w & 3) * 32;   // warp n offset (m16 dim)
    int wm = (w >> 2) * 32;  // warp m offset (n8 dim)

    float d[2][4][4] = {};

#pragma unroll 1
    for (int pass = 0; pass < 2; pass++) {
        const float* A = pass ? jb.A2 : jb.A1;
        const float* W = pass ? jb.W2 : jb.W1;
        int K = pass ? jb.K2 : jb.K1;
        if (K == 0) continue;
        for (int k0 = 0; k0 < K; k0 += 16) {
            // stage W -> Ah/Al (128x16 = 512 float4)
            for (int idx = tid; idx < 512; idx += 256) {
                int n = idx >> 2, kq = (idx & 3) << 2;
                int gn = nblk + n;
                float4 v = make_float4(0.f, 0.f, 0.f, 0.f);
                if (gn < jb.N) v = *(const float4*)(W + (size_t)gn * K + k0 + kq);
                float h0, l0, h1, l1, h2, l2, h3, l3;
                split_tf(v.x, h0, l0); split_tf(v.y, h1, l1);
                split_tf(v.z, h2, l2); split_tf(v.w, h3, l3);
                int b0 = n * 20 + kq;
                Ah[b0] = h0; Ah[b0 + 1] = h1; Ah[b0 + 2] = h2; Ah[b0 + 3] = h3;
                Al[b0] = l0; Al[b0 + 1] = l1; Al[b0 + 2] = l2; Al[b0 + 3] = l3;
            }
            // stage activations -> Bh/Bl (64x16 = 256 float4)
            for (int idx = tid; idx < 256; idx += 256) {
                int m = idx >> 2, kq = (idx & 3) << 2;
                float4 v = *(const float4*)(A + (size_t)(mblk + m) * K + k0 + kq);
                float h0, l0, h1, l1, h2, l2, h3, l3;
                split_tf(v.x, h0, l0); split_tf(v.y, h1, l1);
                split_tf(v.z, h2, l2); split_tf(v.w, h3, l3);
                int b0 = m * 20 + kq;
                Bh[b0] = h0; Bh[b0 + 1] = h1; Bh[b0 + 2] = h2; Bh[b0 + 3] = h3;
                Bl[b0] = l0; Bl[b0 + 1] = l1; Bl[b0 + 2] = l2; Bl[b0 + 3] = l3;
            }
            __syncthreads();
#pragma unroll
            for (int kk = 0; kk < 16; kk += 8) {
                uint32_t ah[2][4], al[2][4], bh[4][2], bl[4][2];
#pragma unroll
                for (int in = 0; in < 2; in++) {
                    int base = (wn + in * 16 + g) * 20 + kk + t;
                    ah[in][0] = __float_as_uint(Ah[base]);
                    ah[in][1] = __float_as_uint(Ah[base + 8 * 20]);
                    ah[in][2] = __float_as_uint(Ah[base + 4]);
                    ah[in][3] = __float_as_uint(Ah[base + 8 * 20 + 4]);
                    al[in][0] = __float_as_uint(Al[base]);
                    al[in][1] = __float_as_uint(Al[base + 8 * 20]);
                    al[in][2] = __float_as_uint(Al[base + 4]);
                    al[in][3] = __float_as_uint(Al[base + 8 * 20 + 4]);
                }
#pragma unroll
                for (int jm = 0; jm < 4; jm++) {
                    int mb = (wm + jm * 8 + g) * 20 + kk + t;
                    bh[jm][0] = __float_as_uint(Bh[mb]);
                    bh[jm][1] = __float_as_uint(Bh[mb + 4]);
                    bl[jm][0] = __float_as_uint(Bl[mb]);
                    bl[jm][1] = __float_as_uint(Bl[mb + 4]);
                }
#pragma unroll
                for (int in = 0; in < 2; in++)
#pragma unroll
                    for (int jm = 0; jm < 4; jm++) {
                        mma8(d[in][jm], ah[in], bl[jm]);
                        mma8(d[in][jm], al[in], bh[jm]);
                        mma8(d[in][jm], ah[in], bh[jm]);
                    }
            }
            __syncthreads();
        }
    }
    // epilogue: D[n][m] -> C[m][n] with bias/act, optional dual write
#pragma unroll
    for (int in = 0; in < 2; in++) {
#pragma unroll
        for (int jm = 0; jm < 4; jm++) {
            int n0 = nblk + wn + in * 16 + g;
            int m0 = mblk + wm + jm * 8 + 2 * t;
            float* r = d[in][jm];
#pragma unroll
            for (int h = 0; h < 2; h++) {          // h=0: row n0, h=1: row n0+8
                int n = n0 + h * 8;
                if (n >= jb.N) continue;
                float bias = (jb.b1 ? jb.b1[n] : 0.f) + (jb.b2 ? jb.b2[n] : 0.f);
#pragma unroll
                for (int q = 0; q < 2; q++) {      // q: m0, m0+1
                    float v = r[h * 2 + q] + bias;
                    if (jb.act == 1) v = tanhf(v);
                    int m = m0 + q;
                    jb.C[(size_t)m * jb.ldc + n] = v;
                    if (jb.C2) jb.C2[(size_t)m * jb.ldc2 + n] = v;
                }
            }
        }
    }
}

// ---------------- LSTM gate elementwise (both nets, one layer) ---------------
__global__ void gates_kernel(const float* __restrict__ Gg, float* __restrict__ cg,
                             float* __restrict__ hg_out,
                             const float* __restrict__ Gw, float* __restrict__ cw,
                             float* __restrict__ hw_out)
{
    const int total_g = BB * HGD;
    const int total_w = BB * HWD;
    int idx = blockIdx.x * blockDim.x + threadIdx.x;
    int stride = gridDim.x * blockDim.x;
    for (int i = idx; i < total_g + total_w; i += stride) {
        const float* G; float* c; float* h; int H; int local;
        if (i < total_g) { G = Gg; c = cg; h = hg_out; H = HGD; local = i; }
        else             { G = Gw; c = cw; h = hw_out; H = HWD; local = i - total_g; }
        int b = local / H, o = local % H;
        const float* gr = G + (size_t)b * 4 * H;
        float gi = gr[o];
        float gf = gr[H + o];
        float gc = gr[2 * H + o];
        float go = gr[3 * H + o];
        float cn = sigf(gf) * c[local] + sigf(gi) * tanhf(gc);
        c[local] = cn;
        h[local] = sigf(go) * tanhf(cn);
    }
}

// ---------------- host ------------------------------------------------------
static TCJob mk(const float* A1, const float* W1, int K1,
                const float* A2, const float* W2, int K2,
                const float* b1, const float* b2,
                float* C, int N, int ldc, int act,
                float* C2 = nullptr, int ldc2 = 0)
{
    TCJob j;
    j.A1 = A1; j.W1 = W1; j.A2 = A2; j.W2 = W2; j.b1 = b1; j.b2 = b2;
    j.C = C; j.C2 = C2;
    j.K1 = K1; j.K2 = K2; j.N = N; j.ldc = ldc; j.ldc2 = ldc2; j.act = act;
    j.nbn = (N + 127) / 128;
    return j;
}

extern "C" void kernel_launch(void* const* d_in, const int* in_sizes, int n_in,
                              void* d_out, int out_size)
{
    const float* ctx    = (const float*)d_in[0];
    const float* goal0  = (const float*)d_in[1];
    const float* w0     = (const float*)d_in[2];
    const float* bg_W   = (const float*)d_in[3];
    const float* bg_b   = (const float*)d_in[4];
    const float* bw_W   = (const float*)d_in[5];
    const float* bw_b   = (const float*)d_in[6];
    const float* fcg_W  = (const float*)d_in[7];
    const float* fcg_b  = (const float*)d_in[8];
    const float* fcw_W  = (const float*)d_in[9];
    const float* fcw_b  = (const float*)d_in[10];
    const float* lg_Wih = (const float*)d_in[11];
    const float* lg_Whh = (const float*)d_in[12];
    const float* lg_bih = (const float*)d_in[13];
    const float* lg_bhh = (const float*)d_in[14];
    const float* lw_Wih = (const float*)d_in[15];
    const float* lw_Whh = (const float*)d_in[16];
    const float* lw_bih = (const float*)d_in[17];
    const float* lw_bhh = (const float*)d_in[18];
    const float* og_W   = (const float*)d_in[19];
    const float* og_b   = (const float*)d_in[20];
    const float* ow_W   = (const float*)d_in[21];
    const float* ow_b   = (const float*)d_in[22];

    float* out   = (float*)d_out;
    float* out_w = out + BB * MS * DOF;

    // scratch addresses
    float *x0, *y0, *x, *y, *Gg, *Gw, *hg, *cg, *hw, *cw, *pgp, *pwp;
    cudaGetSymbolAddress((void**)&x0,  g_x0);
    cudaGetSymbolAddress((void**)&y0,  g_y0);
    cudaGetSymbolAddress((void**)&x,   g_x);
    cudaGetSymbolAddress((void**)&y,   g_y);
    cudaGetSymbolAddress((void**)&Gg,  g_Gg);
    cudaGetSymbolAddress((void**)&Gw,  g_Gw);
    cudaGetSymbolAddress((void**)&hg,  g_hg);
    cudaGetSymbolAddress((void**)&cg,  g_cg);
    cudaGetSymbolAddress((void**)&hw,  g_hw);
    cudaGetSymbolAddress((void**)&cw,  g_cw);
    cudaGetSymbolAddress((void**)&pgp, g_pg);
    cudaGetSymbolAddress((void**)&pwp, g_pw);

    init_kernel<<<512, 256>>>(goal0, w0, out);
    pre_ag_kernel<<<PGD, 256>>>(ctx, bg_W);
    {
        dim3 gAw(2, 5, PWD);   // 128-b tiles x 64-j tiles x 512 o
        pre_aw_tc<<<gAw, 256>>>(ctx, bw_W);
    }

    const int szG = BB * HGD;   // per (layer,parity) slab for g-net
    const int szW = BB * HWD;

    for (int t = 0; t < NSTEP; t++) {
        int p = t & 1;

        bilinear_kernel<<<2304, 256>>>(bg_b, bw_b);

        // FC layers (tanh)
        {
            TCJob a = mk(y0, fcw_W, PWD, nullptr, nullptr, 0, fcw_b, nullptr, y, PWD, PWD, 1);
            TCJob b = mk(x0, fcg_W, PGD, nullptr, nullptr, 0, fcg_b, nullptr, x, PGD, PGD, 1);
            int n0 = 4 * a.nbn;
            tc_gemm2<<<n0 + 4 * b.nbn, 256>>>(a, b, n0);
        }
        // LSTM layer 0 pre-activations
        {
            TCJob a = mk(y, lw_Wih, PWD, hw + (0 * 2 + p) * szW, lw_Whh, HWD,
                         lw_bih, lw_bhh, Gw, 4 * HWD, 4 * HWD, 0);
            TCJob b = mk(x, lg_Wih, PGD, hg + (0 * 2 + p) * szG, lg_Whh, HGD,
                         lg_bih, lg_bhh, Gg, 4 * HGD, 4 * HGD, 0);
            int n0 = 4 * a.nbn;
            tc_gemm2<<<n0 + 4 * b.nbn, 256>>>(a, b, n0);
        }
        gates_kernel<<<768, 256>>>(Gg, cg + 0 * szG, hg + (0 * 2 + (1 - p)) * szG,
                                   Gw, cw + 0 * szW, hw + (0 * 2 + (1 - p)) * szW);
        // LSTM layer 1 pre-activations
        {
            TCJob a = mk(hw + (0 * 2 + (1 - p)) * szW, lw_Wih + 4 * HWD * PWD, HWD,
                         hw + (1 * 2 + p) * szW, lw_Whh + 4 * HWD * HWD, HWD,
                         lw_bih + 4 * HWD, lw_bhh + 4 * HWD, Gw, 4 * HWD, 4 * HWD, 0);
            TCJob b = mk(hg + (0 * 2 + (1 - p)) * szG, lg_Wih + 4 * HGD * PGD, HGD,
                         hg + (1 * 2 + p) * szG, lg_Whh + 4 * HGD * HGD, HGD,
                         lg_bih + 4 * HGD, lg_bhh + 4 * HGD, Gg, 4 * HGD, 4 * HGD, 0);
            int n0 = 4 * a.nbn;
            tc_gemm2<<<n0 + 4 * b.nbn, 256>>>(a, b, n0);
        }
        gates_kernel<<<768, 256>>>(Gg, cg + 1 * szG, hg + (1 * 2 + (1 - p)) * szG,
                                   Gw, cw + 1 * szW, hw + (1 * 2 + (1 - p)) * szW);
        // output heads: also write into d_out slices and pg/pw state
        {
            TCJob a = mk(hw + (1 * 2 + (1 - p)) * szW, ow_W, HWD, nullptr, nullptr, 0,
                         ow_b, nullptr, pwp, WSZ, WSZ, 0,
                         out_w + (t + 1) * WSZ, MS * WSZ);
            TCJob b = mk(hg + (1 * 2 + (1 - p)) * szG, og_W, HGD, nullptr, nullptr, 0,
                         og_b, nullptr, pgp, DOF, DOF, 0,
                         out + (t + 1) * DOF, MS * DOF);
            int n0 = 4 * a.nbn;
            tc_gemm2<<<n0 + 4 * b.nbn, 256>>>(a, b, n0);
        }
    }
}

// round 13
// speedup vs baseline: 1.5131x; 1.5131x over previous
#include <cuda_runtime.h>
#include <cstdint>
#include <math.h>

// Problem constants (fixed by setup_inputs)
#define BB   256   // batch
#define CTXD 512
#define DOF  6
#define WSZ  300
#define ZD   306   // DOF + WSZ
#define PGD  256
#define PWD  512
#define HGD  256
#define HWD  512
#define NL   2
#define MS   20
#define NSTEP (MS - 1)

typedef unsigned long long ull;

// ---------------- scratch (device globals; no runtime allocation) ------------
__device__ __align__(16) float g_Aw[(size_t)PWD * BB * ZD];  // [o][b][j]  (~160MB)
__device__ __align__(16) float g_Ag[BB * PGD * DOF];         // [b][o][j]
__device__ __align__(16) float g_x0[BB * PGD];
__device__ __align__(16) float g_y0[BB * PWD];
__device__ __align__(16) float g_x [BB * PGD];
__device__ __align__(16) float g_y [BB * PWD];
__device__ __align__(16) float g_Gg[BB * 4 * HGD];
__device__ __align__(16) float g_Gw[BB * 4 * HWD];
__device__ __align__(16) float g_hg[NL * 2 * BB * HGD];      // [layer][parity][b*H]
__device__ __align__(16) float g_cg[NL * BB * HGD];
__device__ __align__(16) float g_hw[NL * 2 * BB * HWD];
__device__ __align__(16) float g_cw[NL * BB * HWD];
__device__ __align__(16) float g_pg[BB * DOF];
__device__ __align__(16) float g_pw[BB * WSZ];

__device__ __forceinline__ float sigf(float x) { return 1.f / (1.f + expf(-x)); }

// ---- packed f32x2 FMA (Blackwell FFMA2; per-lane fused RN, exact vs FFMA) ---
__device__ __forceinline__ ull pack2(float lo, float hi) {
    ull r; asm("mov.b64 %0, {%1, %2};" : "=l"(r) : "f"(lo), "f"(hi)); return r;
}
__device__ __forceinline__ float2 unpack2(ull v) {
    float lo, hi; asm("mov.b64 {%0, %1}, %2;" : "=f"(lo), "=f"(hi) : "l"(v));
    float2 f; f.x = lo; f.y = hi; return f;
}
__device__ __forceinline__ void ffma2(ull& d, ull a, ull b) {
    asm("fma.rn.f32x2 %0, %1, %2, %3;" : "=l"(d) : "l"(a), "l"(b), "l"(d));
}

// ---------------- init: zero states, seed pg/pw, write t=0 outputs -----------
__global__ void init_kernel(const float* __restrict__ goal0,
                            const float* __restrict__ w0,
                            float* __restrict__ out)
{
    int tid0 = blockIdx.x * blockDim.x + threadIdx.x;
    int stride = gridDim.x * blockDim.x;
    for (int i = tid0; i < NL * BB * HGD; i += stride) {
        int l = i / (BB * HGD); int r = i % (BB * HGD);
        g_hg[(l * 2 + 0) * BB * HGD + r] = 0.f;
        g_cg[i] = 0.f;
    }
    for (int i = tid0; i < NL * BB * HWD; i += stride) {
        int l = i / (BB * HWD); int r = i % (BB * HWD);
        g_hw[(l * 2 + 0) * BB * HWD + r] = 0.f;
        g_cw[i] = 0.f;
    }
    for (int i = tid0; i < BB * DOF; i += stride) {
        float v = goal0[i];
        g_pg[i] = v;
        int b = i / DOF, d = i % DOF;
        out[b * (MS * DOF) + d] = v;                      // goals[:,0,:]
    }
    for (int i = tid0; i < BB * WSZ; i += stride) {
        float v = w0[i];
        g_pw[i] = v;
        int b = i / WSZ, c = i % WSZ;
        out[BB * MS * DOF + b * (MS * WSZ) + c] = v;      // ws[:,0,:]
    }
}

// ---------------- Ag[b][o][j] = sum_i ctx[b,i] * bgW[o,i,j] ------------------
__global__ void pre_ag_kernel(const float* __restrict__ ctx,
                              const float* __restrict__ bgW)
{
    __shared__ float Ws[CTXD][DOF];  // 12KB
    int o = blockIdx.x;
    const float* Wo = bgW + (size_t)o * CTXD * DOF;
    for (int idx = threadIdx.x; idx < CTXD * DOF; idx += blockDim.x)
        Ws[idx / DOF][idx % DOF] = Wo[idx];
    __syncthreads();
    int b = threadIdx.x;  // blockDim.x == 256
    float acc[DOF] = {0.f, 0.f, 0.f, 0.f, 0.f, 0.f};
    const float* cr = ctx + (size_t)b * CTXD;
    for (int i = 0; i < CTXD; i++) {
        float c = cr[i];
#pragma unroll
        for (int j = 0; j < DOF; j++) acc[j] += c * Ws[i][j];
    }
    float* dst = g_Ag + ((size_t)b * PGD + o) * DOF;
#pragma unroll
    for (int j = 0; j < DOF; j++) dst[j] = acc[j];
}

// ---------------- Aw[o][b][j] = sum_i ctx[b,i] * bwW[o,i,j] ------------------
// Batched GEMM over o: C_o(256x306) = ctx(256x512) @ W_o(512x306)  [FFMA2 core]
__global__ void pre_aw_kernel(const float* __restrict__ ctx,
                              const float* __restrict__ bwW)
{
    int o  = blockIdx.z;
    int bm = blockIdx.x * 64;   // b tile
    int bn = blockIdx.y * 64;   // j tile
    const float* Wo = bwW + (size_t)o * CTXD * ZD;

    __shared__ float As[16][68];
    __shared__ float Bs[16][68];
    ull acc2[4][2] = {};        // 4 m-rows x 2 f32x2 (4 n-cols)
    int tid = threadIdx.x;
    int tx = tid % 16, ty = tid / 16;

    for (int k0 = 0; k0 < CTXD; k0 += 16) {
        {
            int m  = tid >> 2;
            int kq = (tid & 3) * 4;
            float4 v = *(const float4*)(ctx + (size_t)(bm + m) * CTXD + k0 + kq);
            As[kq + 0][m] = v.x; As[kq + 1][m] = v.y;
            As[kq + 2][m] = v.z; As[kq + 3][m] = v.w;
        }
        for (int idx = tid; idx < 16 * 64; idx += 256) {
            int k = idx / 64, n = idx % 64;
            int j = bn + n;
            Bs[k][n] = (j < ZD) ? Wo[(size_t)(k0 + k) * ZD + j] : 0.f;
        }
        __syncthreads();
#pragma unroll
        for (int k = 0; k < 16; k++) {
            float4 av = *(const float4*)&As[k][ty * 4];
            float4 bv = *(const float4*)&Bs[k][tx * 4];
            ull b01 = pack2(bv.x, bv.y);
            ull b23 = pack2(bv.z, bv.w);
            float a[4] = {av.x, av.y, av.z, av.w};
#pragma unroll
            for (int u = 0; u < 4; u++) {
                ull aa = pack2(a[u], a[u]);
                ffma2(acc2[u][0], aa, b01);
                ffma2(acc2[u][1], aa, b23);
            }
        }
        __syncthreads();
    }
    float* base = g_Aw + (size_t)o * BB * ZD;
#pragma unroll
    for (int u = 0; u < 4; u++) {
        int m = bm + ty * 4 + u;
        float2 p0 = unpack2(acc2[u][0]);
        float2 p1 = unpack2(acc2[u][1]);
        float r[4] = {p0.x, p0.y, p1.x, p1.y};
#pragma unroll
        for (int v = 0; v < 4; v++) {
            int j = bn + tx * 4 + v;
            if (j < ZD) base[(size_t)m * ZD + j] = r[v];
        }
    }
}

// ---------------- per-step bilinears: x0 (Ag·pg), y0 (Aw·z) ------------------
__global__ void bilinear_kernel(const float* __restrict__ bg_b,
                                const float* __restrict__ bw_b)
{
    if (blockIdx.x < 2048) {
        int b  = blockIdx.x >> 3;
        int og = (blockIdx.x & 7) * 64;
        __shared__ float zs[320];
        int tid = threadIdx.x;
        for (int i = tid; i < 320; i += 256) {
            float v = 0.f;
            if (i < DOF)      v = g_pg[b * DOF + i];
            else if (i < ZD)  v = g_pw[b * WSZ + (i - DOF)];
            zs[i] = v;
        }
        __syncthreads();
        int warp = tid >> 5, lane = tid & 31;
#pragma unroll
        for (int q = 0; q < 8; q++) {
            int o = og + warp * 8 + q;
            const float* row = g_Aw + ((size_t)o * BB + b) * ZD;
            float acc = 0.f;
            for (int j = lane; j < ZD; j += 32) acc += row[j] * zs[j];
#pragma unroll
            for (int off = 16; off > 0; off >>= 1)
                acc += __shfl_down_sync(0xffffffffu, acc, off);
            if (lane == 0) g_y0[b * PWD + o] = acc + bw_b[o];
        }
    } else {
        int b = blockIdx.x - 2048;
        __shared__ float ps[8];
        if (threadIdx.x < DOF) ps[threadIdx.x] = g_pg[b * DOF + threadIdx.x];
        __syncthreads();
        int o = threadIdx.x;  // 256 threads
        const float* ar = g_Ag + ((size_t)b * PGD + o) * DOF;
        float acc = bg_b[o];
#pragma unroll
        for (int j = 0; j < DOF; j++) acc += ar[j] * ps[j];
        g_x0[b * PGD + o] = acc;
    }
}

// ---------------- generic dual-input GEMM: C = act(A1@W1.T + A2@W2.T + b) ----
// FFMA2 packed-f32 inner product; arithmetic identical to scalar FFMA version.
struct GemmJob {
    const float* A1; const float* W1;
    const float* A2; const float* W2;
    const float* b1; const float* b2;
    float* C;  float* C2;
    int K1, K2, N, ldc, ldc2, act, nbm, nbn;
};

__global__ void gemm2_kernel(GemmJob j0, GemmJob j1, int nblk0)
{
    GemmJob jb = (blockIdx.x < (unsigned)nblk0) ? j0 : j1;
    int local  = blockIdx.x - ((blockIdx.x < (unsigned)nblk0) ? 0 : nblk0);
    int bm = (local % jb.nbm) * 64;
    int bn = (local / jb.nbm) * 64;

    __shared__ float As[16][68];
    __shared__ float Ws[16][68];
    ull acc2[4][2] = {};
    int tid = threadIdx.x;
    int tx = tid % 16, ty = tid / 16;

#pragma unroll 1
    for (int pass = 0; pass < 2; pass++) {
        const float* A = pass ? jb.A2 : jb.A1;
        const float* W = pass ? jb.W2 : jb.W1;
        int K = pass ? jb.K2 : jb.K1;
        if (K == 0) continue;
        for (int k0 = 0; k0 < K; k0 += 16) {
            {
                int m  = tid >> 2;
                int kq = (tid & 3) * 4;
                float4 v = *(const float4*)(A + (size_t)(bm + m) * K + k0 + kq);
                As[kq + 0][m] = v.x; As[kq + 1][m] = v.y;
                As[kq + 2][m] = v.z; As[kq + 3][m] = v.w;
            }
            {
                int n  = tid >> 2;
                int kq = (tid & 3) * 4;
                int gn = bn + n;
                float4 v = make_float4(0.f, 0.f, 0.f, 0.f);
                if (gn < jb.N) v = *(const float4*)(W + (size_t)gn * K + k0 + kq);
                Ws[kq + 0][n] = v.x; Ws[kq + 1][n] = v.y;
                Ws[kq + 2][n] = v.z; Ws[kq + 3][n] = v.w;
            }
            __syncthreads();
#pragma unroll
            for (int k = 0; k < 16; k++) {
                float4 av = *(const float4*)&As[k][ty * 4];
                float4 bv = *(const float4*)&Ws[k][tx * 4];
                ull b01 = pack2(bv.x, bv.y);
                ull b23 = pack2(bv.z, bv.w);
                float a[4] = {av.x, av.y, av.z, av.w};
#pragma unroll
                for (int u = 0; u < 4; u++) {
                    ull aa = pack2(a[u], a[u]);
                    ffma2(acc2[u][0], aa, b01);
                    ffma2(acc2[u][1], aa, b23);
                }
            }
            __syncthreads();
        }
    }
#pragma unroll
    for (int u = 0; u < 4; u++) {
        int m = bm + ty * 4 + u;
        float2 p0 = unpack2(acc2[u][0]);
        float2 p1 = unpack2(acc2[u][1]);
        float r[4] = {p0.x, p0.y, p1.x, p1.y};
#pragma unroll
        for (int v = 0; v < 4; v++) {
            int n = bn + tx * 4 + v;
            if (n < jb.N) {
                float xv = r[v];
                if (jb.b1) xv += jb.b1[n];
                if (jb.b2) xv += jb.b2[n];
                if (jb.act == 1) xv = tanhf(xv);
                jb.C[(size_t)m * jb.ldc + n] = xv;
                if (jb.C2) jb.C2[(size_t)m * jb.ldc2 + n] = xv;
            }
        }
    }
}

// ---------------- LSTM gate elementwise (both nets, one layer) ---------------
__global__ void gates_kernel(const float* __restrict__ Gg, float* __restrict__ cg,
                             float* __restrict__ hg_out,
                             const float* __restrict__ Gw, float* __restrict__ cw,
                             float* __restrict__ hw_out)
{
    const int total_g = BB * HGD;
    const int total_w = BB * HWD;
    int idx = blockIdx.x * blockDim.x + threadIdx.x;
    int stride = gridDim.x * blockDim.x;
    for (int i = idx; i < total_g + total_w; i += stride) {
        const float* G; float* c; float* h; int H; int local;
        if (i < total_g) { G = Gg; c = cg; h = hg_out; H = HGD; local = i; }
        else             { G = Gw; c = cw; h = hw_out; H = HWD; local = i - total_g; }
        int b = local / H, o = local % H;
        const float* gr = G + (size_t)b * 4 * H;
        float gi = gr[o];
        float gf = gr[H + o];
        float gc = gr[2 * H + o];
        float go = gr[3 * H + o];
        float cn = sigf(gf) * c[local] + sigf(gi) * tanhf(gc);
        c[local] = cn;
        h[local] = sigf(go) * tanhf(cn);
    }
}

// ---------------- host ------------------------------------------------------
static GemmJob mk(const float* A1, const float* W1, int K1,
                  const float* A2, const float* W2, int K2,
                  const float* b1, const float* b2,
                  float* C, int N, int ldc, int act,
                  float* C2 = nullptr, int ldc2 = 0)
{
    GemmJob j;
    j.A1 = A1; j.W1 = W1; j.A2 = A2; j.W2 = W2; j.b1 = b1; j.b2 = b2;
    j.C = C; j.C2 = C2;
    j.K1 = K1; j.K2 = K2; j.N = N; j.ldc = ldc; j.ldc2 = ldc2; j.act = act;
    j.nbm = BB / 64; j.nbn = (N + 63) / 64;
    return j;
}

extern "C" void kernel_launch(void* const* d_in, const int* in_sizes, int n_in,
                              void* d_out, int out_size)
{
    const float* ctx    = (const float*)d_in[0];
    const float* goal0  = (const float*)d_in[1];
    const float* w0     = (const float*)d_in[2];
    const float* bg_W   = (const float*)d_in[3];
    const float* bg_b   = (const float*)d_in[4];
    const float* bw_W   = (const float*)d_in[5];
    const float* bw_b   = (const float*)d_in[6];
    const float* fcg_W  = (const float*)d_in[7];
    const float* fcg_b  = (const float*)d_in[8];
    const float* fcw_W  = (const float*)d_in[9];
    const float* fcw_b  = (const float*)d_in[10];
    const float* lg_Wih = (const float*)d_in[11];
    const float* lg_Whh = (const float*)d_in[12];
    const float* lg_bih = (const float*)d_in[13];
    const float* lg_bhh = (const float*)d_in[14];
    const float* lw_Wih = (const float*)d_in[15];
    const float* lw_Whh = (const float*)d_in[16];
    const float* lw_bih = (const float*)d_in[17];
    const float* lw_bhh = (const float*)d_in[18];
    const float* og_W   = (const float*)d_in[19];
    const float* og_b   = (const float*)d_in[20];
    const float* ow_W   = (const float*)d_in[21];
    const float* ow_b   = (const float*)d_in[22];

    float* out   = (float*)d_out;
    float* out_w = out + BB * MS * DOF;

    // scratch addresses
    float *x0, *y0, *x, *y, *Gg, *Gw, *hg, *cg, *hw, *cw, *pgp, *pwp;
    cudaGetSymbolAddress((void**)&x0,  g_x0);
    cudaGetSymbolAddress((void**)&y0,  g_y0);
    cudaGetSymbolAddress((void**)&x,   g_x);
    cudaGetSymbolAddress((void**)&y,   g_y);
    cudaGetSymbolAddress((void**)&Gg,  g_Gg);
    cudaGetSymbolAddress((void**)&Gw,  g_Gw);
    cudaGetSymbolAddress((void**)&hg,  g_hg);
    cudaGetSymbolAddress((void**)&cg,  g_cg);
    cudaGetSymbolAddress((void**)&hw,  g_hw);
    cudaGetSymbolAddress((void**)&cw,  g_cw);
    cudaGetSymbolAddress((void**)&pgp, g_pg);
    cudaGetSymbolAddress((void**)&pwp, g_pw);

    init_kernel<<<512, 256>>>(goal0, w0, out);
    pre_ag_kernel<<<PGD, 256>>>(ctx, bg_W);
    {
        dim3 g(4, 5, PWD);
        pre_aw_kernel<<<g, 256>>>(ctx, bw_W);
    }

    const int szG = BB * HGD;   // per (layer,parity) slab for g-net
    const int szW = BB * HWD;

    for (int t = 0; t < NSTEP; t++) {
        int p = t & 1;

        bilinear_kernel<<<2304, 256>>>(bg_b, bw_b);

        // FC layers (tanh)
        {
            GemmJob a = mk(x0, fcg_W, PGD, nullptr, nullptr, 0, fcg_b, nullptr, x, PGD, PGD, 1);
            GemmJob b = mk(y0, fcw_W, PWD, nullptr, nullptr, 0, fcw_b, nullptr, y, PWD, PWD, 1);
            int n0 = a.nbm * a.nbn;
            gemm2_kernel<<<n0 + b.nbm * b.nbn, 256>>>(a, b, n0);
        }
        // LSTM layer 0 pre-activations
        {
            GemmJob a = mk(x, lg_Wih, PGD, hg + (0 * 2 + p) * szG, lg_Whh, HGD,
                           lg_bih, lg_bhh, Gg, 4 * HGD, 4 * HGD, 0);
            GemmJob b = mk(y, lw_Wih, PWD, hw + (0 * 2 + p) * szW, lw_Whh, HWD,
                           lw_bih, lw_bhh, Gw, 4 * HWD, 4 * HWD, 0);
            int n0 = a.nbm * a.nbn;
            gemm2_kernel<<<n0 + b.nbm * b.nbn, 256>>>(a, b, n0);
        }
        gates_kernel<<<768, 256>>>(Gg, cg + 0 * szG, hg + (0 * 2 + (1 - p)) * szG,
                                   Gw, cw + 0 * szW, hw + (0 * 2 + (1 - p)) * szW);
        // LSTM layer 1 pre-activations
        {
            GemmJob a = mk(hg + (0 * 2 + (1 - p)) * szG, lg_Wih + 4 * HGD * PGD, HGD,
                           hg + (1 * 2 + p) * szG, lg_Whh + 4 * HGD * HGD, HGD,
                           lg_bih + 4 * HGD, lg_bhh + 4 * HGD, Gg, 4 * HGD, 4 * HGD, 0);
            GemmJob b = mk(hw + (0 * 2 + (1 - p)) * szW, lw_Wih + 4 * HWD * PWD, HWD,
                           hw + (1 * 2 + p) * szW, lw_Whh + 4 * HWD * HWD, HWD,
                           lw_bih + 4 * HWD, lw_bhh + 4 * HWD, Gw, 4 * HWD, 4 * HWD, 0);
            int n0 = a.nbm * a.nbn;
            gemm2_kernel<<<n0 + b.nbm * b.nbn, 256>>>(a, b, n0);
        }
        gates_kernel<<<768, 256>>>(Gg, cg + 1 * szG, hg + (1 * 2 + (1 - p)) * szG,
                                   Gw, cw + 1 * szW, hw + (1 * 2 + (1 - p)) * szW);
        // output heads: also write into d_out slices and pg/pw state
        {
            GemmJob a = mk(hw + (1 * 2 + (1 - p)) * szW, ow_W, HWD, nullptr, nullptr, 0,
                           ow_b, nullptr, pwp, WSZ, WSZ, 0,
                           out_w + (t + 1) * WSZ, MS * WSZ);
            GemmJob b = mk(hg + (1 * 2 + (1 - p)) * szG, og_W, HGD, nullptr, nullptr, 0,
                           og_b, nullptr, pgp, DOF, DOF, 0,
                           out + (t + 1) * DOF, MS * DOF);
            int n0 = a.nbm * a.nbn;
            gemm2_kernel<<<n0 + b.nbm * b.nbn, 256>>>(a, b, n0);
        }
    }
}